// round 2
// baseline (speedup 1.0000x reference)
#include <cuda_runtime.h>
#include <cuda_bf16.h>
#include <cstdint>

// ---------------- problem constants ----------------
#define NCELL 512
#define NDRUG 256
#define DCDIM 512
#define DDDIM 278
#define HDIM  512
#define FDIM  64
#define NPOS  (NCELL * NDRUG)          // 131072
#define OUT_FULL (NPOS + NPOS * FDIM)  // 8519680

// ---------------- device scratch ----------------
__device__ float g_cmat[NCELL * HDIM];              // cellpos @ W1[:512]
__device__ float g_dmat[NDRUG * HDIM];              // drugpos @ W1[512:]
__device__ __nv_bfloat16 g_w2t_hi[FDIM * HDIM];     // W2^T split hi  [64,512]
__device__ __nv_bfloat16 g_w2t_lo[FDIM * HDIM];     // W2^T split lo

// ---------------- helpers ----------------
__device__ __forceinline__ uint32_t smem_u32(const void* p) {
    uint32_t a;
    asm("{ .reg .u64 t; cvta.to.shared.u64 t, %1; cvt.u32.u64 %0, t; }"
        : "=r"(a) : "l"(p));
    return a;
}
#define STS128(addr, a, b, c, d) \
    asm volatile("st.shared.v4.b32 [%0], {%1,%2,%3,%4};" \
                 :: "r"(addr), "r"(a), "r"(b), "r"(c), "r"(d) : "memory")
#define LDM4(r, addr) \
    asm volatile("ldmatrix.sync.aligned.m8n8.x4.shared.b16 {%0,%1,%2,%3}, [%4];" \
                 : "=r"((r)[0]), "=r"((r)[1]), "=r"((r)[2]), "=r"((r)[3]) \
                 : "r"(addr))
#define MMA16816(d, a, b0v, b1v) \
    asm volatile("mma.sync.aligned.m16n8k16.row.col.f32.bf16.bf16.f32 " \
                 "{%0,%1,%2,%3}, {%4,%5,%6,%7}, {%8,%9}, {%0,%1,%2,%3};" \
                 : "+f"((d)[0]), "+f"((d)[1]), "+f"((d)[2]), "+f"((d)[3]) \
                 : "r"((a)[0]), "r"((a)[1]), "r"((a)[2]), "r"((a)[3]), \
                   "r"(b0v), "r"(b1v))

// pack two f32 -> bf16x2 (x0 in low half, x1 in high half)
__device__ __forceinline__ uint32_t pack_bf16x2(float x0, float x1) {
    uint32_t r;
    asm("cvt.rn.bf16x2.f32 %0, %1, %2;" : "=r"(r) : "f"(x1), "f"(x0));
    return r;
}
__device__ __forceinline__ float bf_low_f(uint32_t h)  { return __uint_as_float(h << 16); }
__device__ __forceinline__ float bf_high_f(uint32_t h) { return __uint_as_float(h & 0xffff0000u); }

// ---------------- kernel 1: layer-1 GEMMs (fp32) ----------------
__global__ void __launch_bounds__(256) layer1_kernel(const float* __restrict__ cellpos,
                                                     const float* __restrict__ drugpos,
                                                     const float* __restrict__ W1) {
    __shared__ float xs[16 * 512];
    __shared__ float red[16 * 128];
    int b = blockIdx.x;
    const float* X; const float* W; float* out; int K, rt, ct;
    if (b < 128) { rt = b >> 2; ct = b & 3; X = cellpos; W = W1;            out = g_cmat; K = DCDIM; }
    else { int bb = b - 128; rt = bb >> 2; ct = bb & 3; X = drugpos; W = W1 + 512 * 512; out = g_dmat; K = DDDIM; }
    int row0 = rt * 16;
    int tid = threadIdx.x;

    for (int idx = tid; idx < 16 * K; idx += 256) {
        int r = idx / K, k = idx - r * K;
        xs[r * 512 + k] = X[(row0 + r) * K + k];
    }
    __syncthreads();

    int col = ct * 128 + (tid & 127);
    int half = tid >> 7;
    float acc[16];
#pragma unroll
    for (int r = 0; r < 16; r++) acc[r] = 0.f;

    for (int k = half; k < K; k += 2) {
        float w = W[k * 512 + col];
#pragma unroll
        for (int r = 0; r < 16; r++) acc[r] += xs[r * 512 + k] * w;
    }
    __syncthreads();
    if (half == 1) {
#pragma unroll
        for (int r = 0; r < 16; r++) red[r * 128 + (tid & 127)] = acc[r];
    }
    __syncthreads();
    if (half == 0) {
#pragma unroll
        for (int r = 0; r < 16; r++) {
            out[(row0 + r) * 512 + col] = acc[r] + red[r * 128 + (tid & 127)];
        }
    }
}

// ---------------- kernel 2: W2 split+transpose ----------------
__global__ void __launch_bounds__(256) w2split_kernel(const float* __restrict__ W2) {
    int idx = blockIdx.x * 256 + threadIdx.x;
    if (idx < HDIM * FDIM) {
        int k = idx >> 6, n = idx & 63;
        float w = W2[idx];
        __nv_bfloat16 h = __float2bfloat16(w);
        float hf = __bfloat162float(h);
        __nv_bfloat16 l = __float2bfloat16(w - hf);
        g_w2t_hi[n * HDIM + k] = h;
        g_w2t_lo[n * HDIM + k] = l;
    }
}

// ---------------- kernel 3: main fused kernel (mma.sync HMMA path) ----------------
// grid (NCELL, 2): CTA = (cell i, M-half). M=128 drugs, N=64, K=512 in 8 chunks of 64.
// smem rows use 144B pitch (72 bf16) -> conflict-free ldmatrix without swizzle.
#define PITCH 144
#define OFF_H1HI 0
#define OFF_H1LO 18432
#define OFF_W2HI 36864
#define OFF_W2LO 46080
#define OFF_CB   55296
#define OFF_B2   57344
#define OFF_W3   57600
#define DYN_SMEM 58368

__global__ void __launch_bounds__(256, 2) graphcdr_main(const float* __restrict__ b1,
                                                        const float* __restrict__ b2,
                                                        const float* __restrict__ W3,
                                                        const float* __restrict__ b3,
                                                        float* __restrict__ out,
                                                        int out_size) {
    extern __shared__ char smem[];
    const uint32_t sb = smem_u32(smem);

    const int tid  = threadIdx.x;
    const int lane = tid & 31;
    const int w    = tid >> 5;                 // warp 0..7
    const int i    = blockIdx.x;               // cell
    const int jbase = blockIdx.y * 128;        // drug row base

    float* cb  = (float*)(smem + OFF_CB);
    float* b2s = (float*)(smem + OFF_B2);
    float* w3s = (float*)(smem + OFF_W3);
    for (int h = tid; h < HDIM; h += 256) cb[h] = g_cmat[i * HDIM + h] + b1[h];
    if (tid < FDIM) { b2s[tid] = b2[tid]; w3s[tid] = W3[tid]; }

    // fragment smem offsets (per-thread invariants)
    const uint32_t aoff = (uint32_t)((w * 16 + (lane & 15)) * PITCH + ((lane >> 4) * 8) * 2);
    const uint32_t boff = (uint32_t)((((lane >> 4) * 8) + (lane & 7)) * PITCH + ((lane >> 3) & 1) * 16);

    float acc[32];
#pragma unroll
    for (int q = 0; q < 32; q++) acc[q] = 0.f;

    const int frow = tid >> 1;                 // 0..127
    const int fh   = tid & 1;                  // col half (32 cols)
    const int wn   = tid >> 2;                 // w2 row 0..63
    const int wq   = tid & 3;                  // w2 col quarter (16 cols)

    for (int ch = 0; ch < 8; ch++) {
        const int kc = ch << 6;
        __syncthreads();   // prior chunk's MMA reads done before overwrite

        // ---- fill h1 hi/lo: 128 x 64 bf16, pitch 144B ----
        {
            const float* dp = g_dmat + (size_t)(jbase + frow) * HDIM + kc + fh * 32;
            const float* cp = cb + kc + fh * 32;
            const uint32_t dhi = sb + OFF_H1HI + frow * PITCH + fh * 64;
            const uint32_t dlo = sb + OFF_H1LO + frow * PITCH + fh * 64;
#pragma unroll
            for (int q = 0; q < 4; q++) {
                float4 d0 = *(const float4*)(dp + q * 8);
                float4 d1 = *(const float4*)(dp + q * 8 + 4);
                float4 c0 = *(const float4*)(cp + q * 8);
                float4 c1 = *(const float4*)(cp + q * 8 + 4);
                float x0 = fmaxf(c0.x + d0.x, 0.f), x1 = fmaxf(c0.y + d0.y, 0.f);
                float x2 = fmaxf(c0.z + d0.z, 0.f), x3 = fmaxf(c0.w + d0.w, 0.f);
                float x4 = fmaxf(c1.x + d1.x, 0.f), x5 = fmaxf(c1.y + d1.y, 0.f);
                float x6 = fmaxf(c1.z + d1.z, 0.f), x7 = fmaxf(c1.w + d1.w, 0.f);
                uint32_t h0 = pack_bf16x2(x0, x1), h1 = pack_bf16x2(x2, x3);
                uint32_t h2 = pack_bf16x2(x4, x5), h3 = pack_bf16x2(x6, x7);
                uint32_t l0 = pack_bf16x2(x0 - bf_low_f(h0), x1 - bf_high_f(h0));
                uint32_t l1 = pack_bf16x2(x2 - bf_low_f(h1), x3 - bf_high_f(h1));
                uint32_t l2 = pack_bf16x2(x4 - bf_low_f(h2), x5 - bf_high_f(h2));
                uint32_t l3 = pack_bf16x2(x6 - bf_low_f(h3), x7 - bf_high_f(h3));
                STS128(dhi + q * 16, h0, h1, h2, h3);
                STS128(dlo + q * 16, l0, l1, l2, l3);
            }
        }
        // ---- fill W2^T hi/lo: 64 x 64 bf16 ----
        {
            const __nv_bfloat16* sh = g_w2t_hi + (size_t)wn * HDIM + kc + wq * 16;
            const __nv_bfloat16* sl = g_w2t_lo + (size_t)wn * HDIM + kc + wq * 16;
            uint4 vh0 = *(const uint4*)(sh);
            uint4 vh1 = *(const uint4*)(sh + 8);
            uint4 vl0 = *(const uint4*)(sl);
            uint4 vl1 = *(const uint4*)(sl + 8);
            const uint32_t dh = sb + OFF_W2HI + wn * PITCH + wq * 32;
            const uint32_t dl = sb + OFF_W2LO + wn * PITCH + wq * 32;
            STS128(dh,      vh0.x, vh0.y, vh0.z, vh0.w);
            STS128(dh + 16, vh1.x, vh1.y, vh1.z, vh1.w);
            STS128(dl,      vl0.x, vl0.y, vl0.z, vl0.w);
            STS128(dl + 16, vl1.x, vl1.y, vl1.z, vl1.w);
        }
        __syncthreads();

        // ---- MMA: 4 k-steps x 8 ntiles x 3 passes ----
#pragma unroll
        for (int s = 0; s < 4; s++) {
            uint32_t ah[4], al[4];
            LDM4(ah, sb + OFF_H1HI + aoff + s * 32);
            LDM4(al, sb + OFF_H1LO + aoff + s * 32);
            uint32_t bh[16], bl[16];
#pragma unroll
            for (int p = 0; p < 4; p++) {
                LDM4(&bh[p * 4], sb + OFF_W2HI + boff + p * (16 * PITCH) + s * 32);
                LDM4(&bl[p * 4], sb + OFF_W2LO + boff + p * (16 * PITCH) + s * 32);
            }
#pragma unroll
            for (int nt = 0; nt < 8; nt++) {
                const int bi = (nt >> 1) * 4 + (nt & 1) * 2;
                MMA16816(&acc[nt * 4], ah, bh[bi], bh[bi + 1]);
            }
#pragma unroll
            for (int nt = 0; nt < 8; nt++) {
                const int bi = (nt >> 1) * 4 + (nt & 1) * 2;
                MMA16816(&acc[nt * 4], ah, bl[bi], bl[bi + 1]);
            }
#pragma unroll
            for (int nt = 0; nt < 8; nt++) {
                const int bi = (nt >> 1) * 4 + (nt & 1) * 2;
                MMA16816(&acc[nt * 4], al, bh[bi], bh[bi + 1]);
            }
        }
    }

    // ---- epilogue ----
    const float b3v = b3[0];
    const int r  = lane >> 2;
    const int cq = (lane & 3) * 2;
    const int row0 = w * 16 + r;
    const int row1 = row0 + 8;
    const bool wf = (out_size >= OUT_FULL);
    float* featbase = out + NPOS + ((size_t)i * NDRUG + jbase) * FDIM;
    float s0 = 0.f, s1 = 0.f;
#pragma unroll
    for (int nt = 0; nt < 8; nt++) {
        const int c = nt * 8 + cq;
        float v00 = fmaxf(acc[nt * 4 + 0] + b2s[c],     0.f);
        float v01 = fmaxf(acc[nt * 4 + 1] + b2s[c + 1], 0.f);
        float v10 = fmaxf(acc[nt * 4 + 2] + b2s[c],     0.f);
        float v11 = fmaxf(acc[nt * 4 + 3] + b2s[c + 1], 0.f);
        s0 = fmaf(v00, w3s[c], fmaf(v01, w3s[c + 1], s0));
        s1 = fmaf(v10, w3s[c], fmaf(v11, w3s[c + 1], s1));
        if (wf) {
            *(float2*)(featbase + (size_t)row0 * FDIM + c) = make_float2(v00, v01);
            *(float2*)(featbase + (size_t)row1 * FDIM + c) = make_float2(v10, v11);
        }
    }
    s0 += __shfl_xor_sync(0xffffffffu, s0, 1);
    s0 += __shfl_xor_sync(0xffffffffu, s0, 2);
    s1 += __shfl_xor_sync(0xffffffffu, s1, 1);
    s1 += __shfl_xor_sync(0xffffffffu, s1, 2);
    if ((lane & 3) == 0) {
        float g0 = b3v + s0, g1 = b3v + s1;
        out[(size_t)i * NDRUG + jbase + row0] = 1.f / (1.f + expf(-g0));
        out[(size_t)i * NDRUG + jbase + row1] = 1.f / (1.f + expf(-g1));
    }
}

// ---------------- launch ----------------
extern "C" void kernel_launch(void* const* d_in, const int* in_sizes, int n_in,
                              void* d_out, int out_size) {
    if (n_in < 8) return;
    const float* cellpos = (const float*)d_in[0];
    const float* drugpos = (const float*)d_in[1];
    const float* W1      = (const float*)d_in[2];
    const float* b1      = (const float*)d_in[3];
    const float* W2      = (const float*)d_in[4];
    const float* b2      = (const float*)d_in[5];
    const float* W3      = (const float*)d_in[6];
    const float* b3      = (const float*)d_in[7];
    float* out = (float*)d_out;

    layer1_kernel<<<192, 256>>>(cellpos, drugpos, W1);
    w2split_kernel<<<128, 256>>>(W2);

    cudaFuncSetAttribute(graphcdr_main, cudaFuncAttributeMaxDynamicSharedMemorySize, DYN_SMEM);
    graphcdr_main<<<dim3(NCELL, 2), 256, DYN_SMEM>>>(b1, b2, W3, b3, out, out_size);
}

// round 3
// speedup vs baseline: 1.1074x; 1.1074x over previous
#include <cuda_runtime.h>
#include <cuda_bf16.h>
#include <cstdint>

// ---------------- problem constants ----------------
#define NCELL 512
#define NDRUG 256
#define DCDIM 512
#define DDDIM 278
#define HDIM  512
#define FDIM  64
#define NPOS  (NCELL * NDRUG)          // 131072
#define OUT_FULL (NPOS + NPOS * FDIM)  // 8519680

// ---------------- device scratch ----------------
__device__ float g_cmat[NCELL * HDIM];              // cellpos @ W1[:512]
__device__ float g_dmat[NDRUG * HDIM];              // drugpos @ W1[512:]
__device__ __nv_bfloat16 g_w2t_hi[FDIM * HDIM];     // W2^T split hi  [64,512]
__device__ __nv_bfloat16 g_w2t_lo[FDIM * HDIM];     // W2^T split lo

// ---------------- helpers ----------------
__device__ __forceinline__ uint32_t smem_u32(const void* p) {
    uint32_t a;
    asm("{ .reg .u64 t; cvta.to.shared.u64 t, %1; cvt.u32.u64 %0, t; }"
        : "=r"(a) : "l"(p));
    return a;
}
#define STS128(addr, a, b, c, d) \
    asm volatile("st.shared.v4.b32 [%0], {%1,%2,%3,%4};" \
                 :: "r"(addr), "r"(a), "r"(b), "r"(c), "r"(d) : "memory")
#define LDM4(r, addr) \
    asm volatile("ldmatrix.sync.aligned.m8n8.x4.shared.b16 {%0,%1,%2,%3}, [%4];" \
                 : "=r"((r)[0]), "=r"((r)[1]), "=r"((r)[2]), "=r"((r)[3]) \
                 : "r"(addr))
#define MMA16816(d, a, b0v, b1v) \
    asm volatile("mma.sync.aligned.m16n8k16.row.col.f32.bf16.bf16.f32 " \
                 "{%0,%1,%2,%3}, {%4,%5,%6,%7}, {%8,%9}, {%0,%1,%2,%3};" \
                 : "+f"((d)[0]), "+f"((d)[1]), "+f"((d)[2]), "+f"((d)[3]) \
                 : "r"((a)[0]), "r"((a)[1]), "r"((a)[2]), "r"((a)[3]), \
                   "r"(b0v), "r"(b1v))

__device__ __forceinline__ uint32_t pack_bf16x2(float x0, float x1) {
    uint32_t r;
    asm("cvt.rn.bf16x2.f32 %0, %1, %2;" : "=r"(r) : "f"(x1), "f"(x0));
    return r;
}
__device__ __forceinline__ float bf_low_f(uint32_t h)  { return __uint_as_float(h << 16); }
__device__ __forceinline__ float bf_high_f(uint32_t h) { return __uint_as_float(h & 0xffff0000u); }

// ---------------- kernel 1: layer-1 GEMMs (fp32, tiled, double-buffered) ----------------
// C = cellpos[512x512] @ W1[:512]        -> g_cmat
// D = drugpos[256x278] @ W1[512:790]     -> g_dmat
// 64x64 CTA tile, 256 thr, 4x4 micro. Blocks 96..103 do the W2 split.
#define L1_PITCH 68

__global__ void __launch_bounds__(256) layer1_v2(const float* __restrict__ cellpos,
                                                 const float* __restrict__ drugpos,
                                                 const float* __restrict__ W1,
                                                 const float* __restrict__ W2) {
    const int b = blockIdx.x;
    const int tid = threadIdx.x;

    if (b >= 96) {
        // ---- W2 split+transpose: blocks 96..103 cover 512*64 elements ----
        int base = (b - 96) * 4096;
#pragma unroll
        for (int t = 0; t < 16; t++) {
            int idx = base + t * 256 + tid;
            int k = idx >> 6, n = idx & 63;
            float w = W2[idx];
            __nv_bfloat16 h = __float2bfloat16(w);
            float hf = __bfloat162float(h);
            g_w2t_hi[n * HDIM + k] = h;
            g_w2t_lo[n * HDIM + k] = __float2bfloat16(w - hf);
        }
        return;
    }

    __shared__ __align__(16) float As[2][16][L1_PITCH];
    __shared__ __align__(16) float Bs[2][16][L1_PITCH];

    const float* X; const float* W; float* out; int K; bool cpath; int rt, ct;
    if (b < 64) { cpath = true;  rt = b >> 3;        ct = b & 7; X = cellpos; W = W1;             out = g_cmat; K = DCDIM; }
    else        { cpath = false; rt = (b - 64) >> 3; ct = b & 7; X = drugpos; W = W1 + 512 * 512; out = g_dmat; K = DDDIM; }
    const int row0 = rt * 64, col0 = ct * 64;

    const int am = tid >> 2;            // 0..63  (A row within tile)
    const int ak = (tid & 3) * 4;       // 0,4,8,12 (A k within chunk)
    const int bk = tid >> 4;            // 0..15 (B k within chunk)
    const int bn = (tid & 15) * 4;      // B col within tile
    const int nch = (K + 15) >> 4;

    float4 ga, gb;
    // load chunk 0
    if (cpath) {
        ga = *(const float4*)(X + (size_t)(row0 + am) * 512 + ak);
    } else {
        float v0 = (ak + 0 < K) ? X[(size_t)(row0 + am) * DDDIM + ak + 0] : 0.f;
        float v1 = (ak + 1 < K) ? X[(size_t)(row0 + am) * DDDIM + ak + 1] : 0.f;
        float v2 = (ak + 2 < K) ? X[(size_t)(row0 + am) * DDDIM + ak + 2] : 0.f;
        float v3 = (ak + 3 < K) ? X[(size_t)(row0 + am) * DDDIM + ak + 3] : 0.f;
        ga = make_float4(v0, v1, v2, v3);
    }
    gb = (bk < K) ? *(const float4*)(W + (size_t)bk * 512 + col0 + bn)
                  : make_float4(0.f, 0.f, 0.f, 0.f);
    As[0][ak + 0][am] = ga.x; As[0][ak + 1][am] = ga.y;
    As[0][ak + 2][am] = ga.z; As[0][ak + 3][am] = ga.w;
    *(float4*)&Bs[0][bk][bn] = gb;
    __syncthreads();

    const int tn = tid & 15, tm = tid >> 4;
    float acc[4][4] = {};

    for (int t = 0; t < nch; t++) {
        const int cur = t & 1;
        if (t + 1 < nch) {
            const int k0 = (t + 1) << 4;
            if (cpath) {
                ga = *(const float4*)(X + (size_t)(row0 + am) * 512 + k0 + ak);
            } else {
                float v0 = (k0 + ak + 0 < K) ? X[(size_t)(row0 + am) * DDDIM + k0 + ak + 0] : 0.f;
                float v1 = (k0 + ak + 1 < K) ? X[(size_t)(row0 + am) * DDDIM + k0 + ak + 1] : 0.f;
                float v2 = (k0 + ak + 2 < K) ? X[(size_t)(row0 + am) * DDDIM + k0 + ak + 2] : 0.f;
                float v3 = (k0 + ak + 3 < K) ? X[(size_t)(row0 + am) * DDDIM + k0 + ak + 3] : 0.f;
                ga = make_float4(v0, v1, v2, v3);
            }
            gb = (k0 + bk < K) ? *(const float4*)(W + (size_t)(k0 + bk) * 512 + col0 + bn)
                               : make_float4(0.f, 0.f, 0.f, 0.f);
        }
#pragma unroll
        for (int k = 0; k < 16; k++) {
            float4 a4 = *(const float4*)&As[cur][k][tm * 4];
            float4 b4 = *(const float4*)&Bs[cur][k][tn * 4];
            acc[0][0] = fmaf(a4.x, b4.x, acc[0][0]); acc[0][1] = fmaf(a4.x, b4.y, acc[0][1]);
            acc[0][2] = fmaf(a4.x, b4.z, acc[0][2]); acc[0][3] = fmaf(a4.x, b4.w, acc[0][3]);
            acc[1][0] = fmaf(a4.y, b4.x, acc[1][0]); acc[1][1] = fmaf(a4.y, b4.y, acc[1][1]);
            acc[1][2] = fmaf(a4.y, b4.z, acc[1][2]); acc[1][3] = fmaf(a4.y, b4.w, acc[1][3]);
            acc[2][0] = fmaf(a4.z, b4.x, acc[2][0]); acc[2][1] = fmaf(a4.z, b4.y, acc[2][1]);
            acc[2][2] = fmaf(a4.z, b4.z, acc[2][2]); acc[2][3] = fmaf(a4.z, b4.w, acc[2][3]);
            acc[3][0] = fmaf(a4.w, b4.x, acc[3][0]); acc[3][1] = fmaf(a4.w, b4.y, acc[3][1]);
            acc[3][2] = fmaf(a4.w, b4.z, acc[3][2]); acc[3][3] = fmaf(a4.w, b4.w, acc[3][3]);
        }
        if (t + 1 < nch) {
            const int nxt = cur ^ 1;
            As[nxt][ak + 0][am] = ga.x; As[nxt][ak + 1][am] = ga.y;
            As[nxt][ak + 2][am] = ga.z; As[nxt][ak + 3][am] = ga.w;
            *(float4*)&Bs[nxt][bk][bn] = gb;
        }
        __syncthreads();
    }

#pragma unroll
    for (int r = 0; r < 4; r++) {
        *(float4*)(out + (size_t)(row0 + tm * 4 + r) * 512 + col0 + tn * 4) =
            make_float4(acc[r][0], acc[r][1], acc[r][2], acc[r][3]);
    }
}

// ---------------- kernel 2: main fused kernel (HMMA, reg-prefetched) ----------------
#define PITCH 144
#define OFF_H1HI 0
#define OFF_H1LO 18432
#define OFF_W2HI 36864
#define OFF_W2LO 46080
#define OFF_CB   55296
#define OFF_B2   57344
#define OFF_W3   57600
#define DYN_SMEM 58368

__global__ void __launch_bounds__(256, 2) graphcdr_main(const float* __restrict__ b1,
                                                        const float* __restrict__ b2,
                                                        const float* __restrict__ W3,
                                                        const float* __restrict__ b3,
                                                        float* __restrict__ out,
                                                        int out_size) {
    extern __shared__ char smem[];
    const uint32_t sb = smem_u32(smem);

    const int tid  = threadIdx.x;
    const int lane = tid & 31;
    const int w    = tid >> 5;                 // warp 0..7
    const int i    = blockIdx.x;               // cell
    const int jbase = blockIdx.y * 128;        // drug row base

    float* cb  = (float*)(smem + OFF_CB);
    float* b2s = (float*)(smem + OFF_B2);
    float* w3s = (float*)(smem + OFF_W3);
    for (int h = tid; h < HDIM; h += 256) cb[h] = g_cmat[i * HDIM + h] + b1[h];
    if (tid < FDIM) { b2s[tid] = b2[tid]; w3s[tid] = W3[tid]; }

    // fragment smem offsets
    const uint32_t aoff = (uint32_t)((w * 16 + (lane & 15)) * PITCH + ((lane >> 4) * 8) * 2);
    const uint32_t boff = (uint32_t)((((lane >> 4) * 8) + (lane & 7)) * PITCH + ((lane >> 3) & 1) * 16);

    float acc[32];
#pragma unroll
    for (int q = 0; q < 32; q++) acc[q] = 0.f;

    const int frow = tid >> 1;                 // 0..127
    const int fh   = tid & 1;                  // col half (32 cols)
    const int wn   = tid >> 2;                 // w2 row 0..63
    const int wq   = tid & 3;                  // w2 col quarter

    const float* dbase = g_dmat + (size_t)(jbase + frow) * HDIM + fh * 32;
    const __nv_bfloat16* whbase = g_w2t_hi + (size_t)wn * HDIM + wq * 16;
    const __nv_bfloat16* wlbase = g_w2t_lo + (size_t)wn * HDIM + wq * 16;

    // prefetch registers
    float4 dA[8];
    uint4 vh0, vh1, vl0, vl1;
    {
        const float* dp = dbase;   // chunk 0 (kc = 0)
#pragma unroll
        for (int q = 0; q < 4; q++) {
            dA[q * 2]     = *(const float4*)(dp + q * 8);
            dA[q * 2 + 1] = *(const float4*)(dp + q * 8 + 4);
        }
        vh0 = *(const uint4*)(whbase);     vh1 = *(const uint4*)(whbase + 8);
        vl0 = *(const uint4*)(wlbase);     vl1 = *(const uint4*)(wlbase + 8);
    }

    for (int ch = 0; ch < 8; ch++) {
        const int kc = ch << 6;
        __syncthreads();   // prior MMA reads done (and cb ready at ch==0)

        // ---- pack+store h1 hi/lo from prefetched regs ----
        {
            const float* cp = cb + kc + fh * 32;
            const uint32_t dhi = sb + OFF_H1HI + frow * PITCH + fh * 64;
            const uint32_t dlo = sb + OFF_H1LO + frow * PITCH + fh * 64;
#pragma unroll
            for (int q = 0; q < 4; q++) {
                float4 d0 = dA[q * 2], d1 = dA[q * 2 + 1];
                float4 c0 = *(const float4*)(cp + q * 8);
                float4 c1 = *(const float4*)(cp + q * 8 + 4);
                float x0 = fmaxf(c0.x + d0.x, 0.f), x1 = fmaxf(c0.y + d0.y, 0.f);
                float x2 = fmaxf(c0.z + d0.z, 0.f), x3 = fmaxf(c0.w + d0.w, 0.f);
                float x4 = fmaxf(c1.x + d1.x, 0.f), x5 = fmaxf(c1.y + d1.y, 0.f);
                float x6 = fmaxf(c1.z + d1.z, 0.f), x7 = fmaxf(c1.w + d1.w, 0.f);
                uint32_t h0 = pack_bf16x2(x0, x1), h1 = pack_bf16x2(x2, x3);
                uint32_t h2 = pack_bf16x2(x4, x5), h3 = pack_bf16x2(x6, x7);
                uint32_t l0 = pack_bf16x2(x0 - bf_low_f(h0), x1 - bf_high_f(h0));
                uint32_t l1 = pack_bf16x2(x2 - bf_low_f(h1), x3 - bf_high_f(h1));
                uint32_t l2 = pack_bf16x2(x4 - bf_low_f(h2), x5 - bf_high_f(h2));
                uint32_t l3 = pack_bf16x2(x6 - bf_low_f(h3), x7 - bf_high_f(h3));
                STS128(dhi + q * 16, h0, h1, h2, h3);
                STS128(dlo + q * 16, l0, l1, l2, l3);
            }
        }
        // ---- store W2^T hi/lo from prefetched regs ----
        {
            const uint32_t dh = sb + OFF_W2HI + wn * PITCH + wq * 32;
            const uint32_t dl = sb + OFF_W2LO + wn * PITCH + wq * 32;
            STS128(dh,      vh0.x, vh0.y, vh0.z, vh0.w);
            STS128(dh + 16, vh1.x, vh1.y, vh1.z, vh1.w);
            STS128(dl,      vl0.x, vl0.y, vl0.z, vl0.w);
            STS128(dl + 16, vl1.x, vl1.y, vl1.z, vl1.w);
        }
        __syncthreads();

        // ---- prefetch next chunk while MMAs run ----
        if (ch < 7) {
            const int kn = kc + 64;
            const float* dp = dbase + kn;
#pragma unroll
            for (int q = 0; q < 4; q++) {
                dA[q * 2]     = *(const float4*)(dp + q * 8);
                dA[q * 2 + 1] = *(const float4*)(dp + q * 8 + 4);
            }
            vh0 = *(const uint4*)(whbase + kn);     vh1 = *(const uint4*)(whbase + kn + 8);
            vl0 = *(const uint4*)(wlbase + kn);     vl1 = *(const uint4*)(wlbase + kn + 8);
        }

        // ---- MMA: 4 k-steps x (4 p-groups x {hh, h*lo, lo*h}) ----
#pragma unroll
        for (int s = 0; s < 4; s++) {
            uint32_t ah[4], al[4];
            LDM4(ah, sb + OFF_H1HI + aoff + s * 32);
            LDM4(al, sb + OFF_H1LO + aoff + s * 32);
#pragma unroll
            for (int p = 0; p < 4; p++) {
                uint32_t bh4[4], bl4[4];
                LDM4(bh4, sb + OFF_W2HI + boff + p * (16 * PITCH) + s * 32);
                LDM4(bl4, sb + OFF_W2LO + boff + p * (16 * PITCH) + s * 32);
                float* a0 = &acc[(p * 2) * 4];
                float* a1 = &acc[(p * 2 + 1) * 4];
                MMA16816(a0, ah, bh4[0], bh4[1]);
                MMA16816(a1, ah, bh4[2], bh4[3]);
                MMA16816(a0, ah, bl4[0], bl4[1]);
                MMA16816(a1, ah, bl4[2], bl4[3]);
                MMA16816(a0, al, bh4[0], bh4[1]);
                MMA16816(a1, al, bh4[2], bh4[3]);
            }
        }
    }

    // ---- epilogue ----
    const float b3v = b3[0];
    const int r  = lane >> 2;
    const int cq = (lane & 3) * 2;
    const int row0 = w * 16 + r;
    const int row1 = row0 + 8;
    const bool wf = (out_size >= OUT_FULL);
    float* featbase = out + NPOS + ((size_t)i * NDRUG + jbase) * FDIM;
    float s0 = 0.f, s1 = 0.f;
#pragma unroll
    for (int nt = 0; nt < 8; nt++) {
        const int c = nt * 8 + cq;
        float v00 = fmaxf(acc[nt * 4 + 0] + b2s[c],     0.f);
        float v01 = fmaxf(acc[nt * 4 + 1] + b2s[c + 1], 0.f);
        float v10 = fmaxf(acc[nt * 4 + 2] + b2s[c],     0.f);
        float v11 = fmaxf(acc[nt * 4 + 3] + b2s[c + 1], 0.f);
        s0 = fmaf(v00, w3s[c], fmaf(v01, w3s[c + 1], s0));
        s1 = fmaf(v10, w3s[c], fmaf(v11, w3s[c + 1], s1));
        if (wf) {
            *(float2*)(featbase + (size_t)row0 * FDIM + c) = make_float2(v00, v01);
            *(float2*)(featbase + (size_t)row1 * FDIM + c) = make_float2(v10, v11);
        }
    }
    s0 += __shfl_xor_sync(0xffffffffu, s0, 1);
    s0 += __shfl_xor_sync(0xffffffffu, s0, 2);
    s1 += __shfl_xor_sync(0xffffffffu, s1, 1);
    s1 += __shfl_xor_sync(0xffffffffu, s1, 2);
    if ((lane & 3) == 0) {
        out[(size_t)i * NDRUG + jbase + row0] = 1.f / (1.f + expf(-(b3v + s0)));
        out[(size_t)i * NDRUG + jbase + row1] = 1.f / (1.f + expf(-(b3v + s1)));
    }
}

// ---------------- launch ----------------
extern "C" void kernel_launch(void* const* d_in, const int* in_sizes, int n_in,
                              void* d_out, int out_size) {
    if (n_in < 8) return;
    const float* cellpos = (const float*)d_in[0];
    const float* drugpos = (const float*)d_in[1];
    const float* W1      = (const float*)d_in[2];
    const float* b1      = (const float*)d_in[3];
    const float* W2      = (const float*)d_in[4];
    const float* b2      = (const float*)d_in[5];
    const float* W3      = (const float*)d_in[6];
    const float* b3      = (const float*)d_in[7];
    float* out = (float*)d_out;

    layer1_v2<<<104, 256>>>(cellpos, drugpos, W1, W2);

    cudaFuncSetAttribute(graphcdr_main, cudaFuncAttributeMaxDynamicSharedMemorySize, DYN_SMEM);
    graphcdr_main<<<dim3(NCELL, 2), 256, DYN_SMEM>>>(b1, b2, W3, b3, out, out_size);
}

// round 4
// speedup vs baseline: 1.9028x; 1.7182x over previous
#include <cuda_runtime.h>
#include <cuda_bf16.h>
#include <cstdint>

// ---------------- problem constants ----------------
#define NCELL 512
#define NDRUG 256
#define DCDIM 512
#define DDDIM 278
#define HDIM  512
#define FDIM  64
#define NPOS  (NCELL * NDRUG)          // 131072
#define OUT_FULL (NPOS + NPOS * FDIM)  // 8519680

// ---------------- device scratch ----------------
__device__ float g_cmat[NCELL * HDIM];              // cellpos @ W1[:512]
__device__ float g_dmat[NDRUG * HDIM];              // drugpos @ W1[512:]
// B fragments in exact mma register order:
// index ((ch*4+s)*4+p)*64 + lane*2  -> [hi uint4, lo uint4]
__device__ uint4 g_w2frag[8 * 4 * 4 * 32 * 2];      // 128 KB

// ---------------- helpers ----------------
__device__ __forceinline__ uint32_t smem_u32(const void* p) {
    uint32_t a;
    asm("{ .reg .u64 t; cvta.to.shared.u64 t, %1; cvt.u32.u64 %0, t; }"
        : "=r"(a) : "l"(p));
    return a;
}
#define LDM4(r, addr) \
    asm volatile("ldmatrix.sync.aligned.m8n8.x4.shared.b16 {%0,%1,%2,%3}, [%4];" \
                 : "=r"((r)[0]), "=r"((r)[1]), "=r"((r)[2]), "=r"((r)[3]) \
                 : "r"(addr))
#define MMA16816(d, a, b0v, b1v) \
    asm volatile("mma.sync.aligned.m16n8k16.row.col.f32.bf16.bf16.f32 " \
                 "{%0,%1,%2,%3}, {%4,%5,%6,%7}, {%8,%9}, {%0,%1,%2,%3};" \
                 : "+f"((d)[0]), "+f"((d)[1]), "+f"((d)[2]), "+f"((d)[3]) \
                 : "r"((a)[0]), "r"((a)[1]), "r"((a)[2]), "r"((a)[3]), \
                   "r"(b0v), "r"(b1v))

__device__ __forceinline__ uint32_t pack_bf16x2(float x0, float x1) {
    uint32_t r;
    asm("cvt.rn.bf16x2.f32 %0, %1, %2;" : "=r"(r) : "f"(x1), "f"(x0));
    return r;
}
__device__ __forceinline__ float bf_low_f(uint32_t h)  { return __uint_as_float(h << 16); }
__device__ __forceinline__ float bf_high_f(uint32_t h) { return __uint_as_float(h & 0xffff0000u); }

// ---------------- kernel 1: layer-1 GEMMs + W2 fragment precompute ----------------
#define L1_PITCH 68

__global__ void __launch_bounds__(256) layer1_v2(const float* __restrict__ cellpos,
                                                 const float* __restrict__ drugpos,
                                                 const float* __restrict__ W1,
                                                 const float* __restrict__ W2) {
    const int b = blockIdx.x;
    const int tid = threadIdx.x;

    if (b >= 96) {
        // ---- W2 -> split bf16 hi/lo -> ldmatrix fragments -> g_w2frag ----
        const int ch = b - 96;                       // k-chunk 0..7
        __shared__ __nv_bfloat16 hi[64][72];         // [n][k], 144B pitch
        __shared__ __nv_bfloat16 lo[64][72];
#pragma unroll
        for (int t = 0; t < 16; t++) {
            int idx = t * 256 + tid;                 // 0..4095
            int n = idx >> 6, kk = idx & 63;
            float wv = W2[(ch * 64 + kk) * 64 + n];  // W2 is [k][n]
            __nv_bfloat16 h = __float2bfloat16(wv);
            hi[n][kk] = h;
            lo[n][kk] = __float2bfloat16(wv - __bfloat162float(h));
        }
        __syncthreads();
        const int w8 = tid >> 5, lane = tid & 31;
        const int s = w8 >> 1;                       // k-step 0..3
        const int p0 = (w8 & 1) * 2;                 // n-group pair
        const uint32_t hbase = smem_u32(&hi[0][0]);
        const uint32_t lbase = smem_u32(&lo[0][0]);
        const uint32_t boff = (uint32_t)((((lane >> 4) * 8) + (lane & 7)) * 144 + ((lane >> 3) & 1) * 16);
#pragma unroll
        for (int q = 0; q < 2; q++) {
            const int p = p0 + q;
            uint32_t bh4[4], bl4[4];
            LDM4(bh4, hbase + boff + p * (16 * 144) + s * 32);
            LDM4(bl4, lbase + boff + p * (16 * 144) + s * 32);
            uint4* dst = g_w2frag + (((size_t)(ch * 4 + s) * 4 + p) * 64 + lane * 2);
            dst[0] = make_uint4(bh4[0], bh4[1], bh4[2], bh4[3]);
            dst[1] = make_uint4(bl4[0], bl4[1], bl4[2], bl4[3]);
        }
        return;
    }

    __shared__ __align__(16) float As[2][16][L1_PITCH];
    __shared__ __align__(16) float Bs[2][16][L1_PITCH];

    const float* X; const float* W; float* out; int K; bool cpath; int rt, ct;
    if (b < 64) { cpath = true;  rt = b >> 3;        ct = b & 7; X = cellpos; W = W1;             out = g_cmat; K = DCDIM; }
    else        { cpath = false; rt = (b - 64) >> 3; ct = b & 7; X = drugpos; W = W1 + 512 * 512; out = g_dmat; K = DDDIM; }
    const int row0 = rt * 64, col0 = ct * 64;

    const int am = tid >> 2;
    const int ak = (tid & 3) * 4;
    const int bk = tid >> 4;
    const int bn = (tid & 15) * 4;
    const int nch = (K + 15) >> 4;

    float4 ga, gb;
    if (cpath) {
        ga = *(const float4*)(X + (size_t)(row0 + am) * 512 + ak);
    } else {
        float v0 = (ak + 0 < K) ? X[(size_t)(row0 + am) * DDDIM + ak + 0] : 0.f;
        float v1 = (ak + 1 < K) ? X[(size_t)(row0 + am) * DDDIM + ak + 1] : 0.f;
        float v2 = (ak + 2 < K) ? X[(size_t)(row0 + am) * DDDIM + ak + 2] : 0.f;
        float v3 = (ak + 3 < K) ? X[(size_t)(row0 + am) * DDDIM + ak + 3] : 0.f;
        ga = make_float4(v0, v1, v2, v3);
    }
    gb = (bk < K) ? *(const float4*)(W + (size_t)bk * 512 + col0 + bn)
                  : make_float4(0.f, 0.f, 0.f, 0.f);
    As[0][ak + 0][am] = ga.x; As[0][ak + 1][am] = ga.y;
    As[0][ak + 2][am] = ga.z; As[0][ak + 3][am] = ga.w;
    *(float4*)&Bs[0][bk][bn] = gb;
    __syncthreads();

    const int tn = tid & 15, tm = tid >> 4;
    float acc[4][4] = {};

    for (int t = 0; t < nch; t++) {
        const int cur = t & 1;
        if (t + 1 < nch) {
            const int k0 = (t + 1) << 4;
            if (cpath) {
                ga = *(const float4*)(X + (size_t)(row0 + am) * 512 + k0 + ak);
            } else {
                float v0 = (k0 + ak + 0 < K) ? X[(size_t)(row0 + am) * DDDIM + k0 + ak + 0] : 0.f;
                float v1 = (k0 + ak + 1 < K) ? X[(size_t)(row0 + am) * DDDIM + k0 + ak + 1] : 0.f;
                float v2 = (k0 + ak + 2 < K) ? X[(size_t)(row0 + am) * DDDIM + k0 + ak + 2] : 0.f;
                float v3 = (k0 + ak + 3 < K) ? X[(size_t)(row0 + am) * DDDIM + k0 + ak + 3] : 0.f;
                ga = make_float4(v0, v1, v2, v3);
            }
            gb = (k0 + bk < K) ? *(const float4*)(W + (size_t)(k0 + bk) * 512 + col0 + bn)
                               : make_float4(0.f, 0.f, 0.f, 0.f);
        }
#pragma unroll
        for (int k = 0; k < 16; k++) {
            float4 a4 = *(const float4*)&As[cur][k][tm * 4];
            float4 b4 = *(const float4*)&Bs[cur][k][tn * 4];
            acc[0][0] = fmaf(a4.x, b4.x, acc[0][0]); acc[0][1] = fmaf(a4.x, b4.y, acc[0][1]);
            acc[0][2] = fmaf(a4.x, b4.z, acc[0][2]); acc[0][3] = fmaf(a4.x, b4.w, acc[0][3]);
            acc[1][0] = fmaf(a4.y, b4.x, acc[1][0]); acc[1][1] = fmaf(a4.y, b4.y, acc[1][1]);
            acc[1][2] = fmaf(a4.y, b4.z, acc[1][2]); acc[1][3] = fmaf(a4.y, b4.w, acc[1][3]);
            acc[2][0] = fmaf(a4.z, b4.x, acc[2][0]); acc[2][1] = fmaf(a4.z, b4.y, acc[2][1]);
            acc[2][2] = fmaf(a4.z, b4.z, acc[2][2]); acc[2][3] = fmaf(a4.z, b4.w, acc[2][3]);
            acc[3][0] = fmaf(a4.w, b4.x, acc[3][0]); acc[3][1] = fmaf(a4.w, b4.y, acc[3][1]);
            acc[3][2] = fmaf(a4.w, b4.z, acc[3][2]); acc[3][3] = fmaf(a4.w, b4.w, acc[3][3]);
        }
        if (t + 1 < nch) {
            const int nxt = cur ^ 1;
            As[nxt][ak + 0][am] = ga.x; As[nxt][ak + 1][am] = ga.y;
            As[nxt][ak + 2][am] = ga.z; As[nxt][ak + 3][am] = ga.w;
            *(float4*)&Bs[nxt][bk][bn] = gb;
        }
        __syncthreads();
    }

#pragma unroll
    for (int r = 0; r < 4; r++) {
        *(float4*)(out + (size_t)(row0 + tm * 4 + r) * 512 + col0 + tn * 4) =
            make_float4(acc[r][0], acc[r][1], acc[r][2], acc[r][3]);
    }
}

// ---------------- kernel 2: main fused kernel (A in regs, B via frag LDG) ----------------
// grid (NCELL, 2), 128 threads. Warp tile: 32 rows x 64 cols. No smem in mainloop.
__global__ void __launch_bounds__(128, 3) graphcdr_main(const float* __restrict__ b1,
                                                        const float* __restrict__ b2,
                                                        const float* __restrict__ W3,
                                                        const float* __restrict__ b3,
                                                        float* __restrict__ out,
                                                        int out_size) {
    __shared__ float cb[HDIM];
    __shared__ float b2s[FDIM];
    __shared__ float w3s[FDIM];

    const int tid  = threadIdx.x;
    const int lane = tid & 31;
    const int w    = tid >> 5;                 // warp 0..3
    const int i    = blockIdx.x;               // cell
    const int jbase = blockIdx.y * 128;        // drug row base

#pragma unroll
    for (int q = 0; q < 4; q++) cb[q * 128 + tid] = g_cmat[i * HDIM + q * 128 + tid] + b1[q * 128 + tid];
    if (tid < FDIM) { b2s[tid] = b2[tid]; w3s[tid] = W3[tid]; }
    __syncthreads();

    // per-thread d pointer: row = jbase + w*32 + (lane>>2), col = 2*(lane&3)
    const float* dp0 = g_dmat + (size_t)(jbase + w * 32 + (lane >> 2)) * HDIM + 2 * (lane & 3);

    float acc[16][4];
#pragma unroll
    for (int q = 0; q < 16; q++) {
        acc[q][0] = 0.f; acc[q][1] = 0.f; acc[q][2] = 0.f; acc[q][3] = 0.f;
    }

    // d values for current s: dv[mt][4]: (R,k),(R+8,k),(R,k+8),(R+8,k+8) as float2
    float2 dv[2][4];
#pragma unroll
    for (int mt = 0; mt < 2; mt++) {
        const float* p = dp0 + mt * (16 * HDIM);
        dv[mt][0] = *(const float2*)(p);
        dv[mt][1] = *(const float2*)(p + 8 * HDIM);
        dv[mt][2] = *(const float2*)(p + 8);
        dv[mt][3] = *(const float2*)(p + 8 * HDIM + 8);
    }

    const int laneK = 2 * (lane & 3);

    for (int ch = 0; ch < 8; ch++) {
#pragma unroll
        for (int s = 0; s < 4; s++) {
            const int kk = ch * 64 + s * 16 + laneK;
            const float2 cb0 = *(const float2*)&cb[kk];
            const float2 cb1 = *(const float2*)&cb[kk + 8];

            uint32_t ah[2][4], al[2][4];
#pragma unroll
            for (int mt = 0; mt < 2; mt++) {
                float x0 = fmaxf(cb0.x + dv[mt][0].x, 0.f);
                float x1 = fmaxf(cb0.y + dv[mt][0].y, 0.f);
                float y0 = fmaxf(cb0.x + dv[mt][1].x, 0.f);
                float y1 = fmaxf(cb0.y + dv[mt][1].y, 0.f);
                float x2 = fmaxf(cb1.x + dv[mt][2].x, 0.f);
                float x3 = fmaxf(cb1.y + dv[mt][2].y, 0.f);
                float y2 = fmaxf(cb1.x + dv[mt][3].x, 0.f);
                float y3 = fmaxf(cb1.y + dv[mt][3].y, 0.f);
                uint32_t h0 = pack_bf16x2(x0, x1);
                uint32_t h1 = pack_bf16x2(y0, y1);
                uint32_t h2 = pack_bf16x2(x2, x3);
                uint32_t h3 = pack_bf16x2(y2, y3);
                ah[mt][0] = h0; ah[mt][1] = h1; ah[mt][2] = h2; ah[mt][3] = h3;
                al[mt][0] = pack_bf16x2(x0 - bf_low_f(h0), x1 - bf_high_f(h0));
                al[mt][1] = pack_bf16x2(y0 - bf_low_f(h1), y1 - bf_high_f(h1));
                al[mt][2] = pack_bf16x2(x2 - bf_low_f(h2), x3 - bf_high_f(h2));
                al[mt][3] = pack_bf16x2(y2 - bf_low_f(h3), y3 - bf_high_f(h3));
            }

            // prefetch d for next s
            if (ch * 4 + s < 31) {
                const int kn = ch * 64 + (s + 1) * 16;
#pragma unroll
                for (int mt = 0; mt < 2; mt++) {
                    const float* p = dp0 + mt * (16 * HDIM) + kn;
                    dv[mt][0] = *(const float2*)(p);
                    dv[mt][1] = *(const float2*)(p + 8 * HDIM);
                    dv[mt][2] = *(const float2*)(p + 8);
                    dv[mt][3] = *(const float2*)(p + 8 * HDIM + 8);
                }
            }

            const uint4* fb = g_w2frag + ((size_t)(ch * 4 + s) * 4) * 64 + lane * 2;
#pragma unroll
            for (int p = 0; p < 4; p++) {
                const uint4 bh = fb[p * 64];
                const uint4 bl = fb[p * 64 + 1];
#pragma unroll
                for (int mt = 0; mt < 2; mt++) {
                    float* a0 = acc[mt * 8 + p * 2];
                    float* a1 = acc[mt * 8 + p * 2 + 1];
                    MMA16816(a0, ah[mt], bh.x, bh.y);
                    MMA16816(a1, ah[mt], bh.z, bh.w);
                    MMA16816(a0, ah[mt], bl.x, bl.y);
                    MMA16816(a1, ah[mt], bl.z, bl.w);
                    MMA16816(a0, al[mt], bh.x, bh.y);
                    MMA16816(a1, al[mt], bh.z, bh.w);
                }
            }
        }
    }

    // ---- epilogue ----
    const float b3v = b3[0];
    const int r  = lane >> 2;
    const int cq = 2 * (lane & 3);
    const bool wf = (out_size >= OUT_FULL);
#pragma unroll
    for (int mt = 0; mt < 2; mt++) {
        const int row0 = jbase + w * 32 + mt * 16 + r;   // drug row
        const int row1 = row0 + 8;
        float* featbase = out + NPOS + ((size_t)i * NDRUG) * FDIM;
        float s0 = 0.f, s1 = 0.f;
#pragma unroll
        for (int nt = 0; nt < 8; nt++) {
            const int c = nt * 8 + cq;
            float v00 = fmaxf(acc[mt * 8 + nt][0] + b2s[c],     0.f);
            float v01 = fmaxf(acc[mt * 8 + nt][1] + b2s[c + 1], 0.f);
            float v10 = fmaxf(acc[mt * 8 + nt][2] + b2s[c],     0.f);
            float v11 = fmaxf(acc[mt * 8 + nt][3] + b2s[c + 1], 0.f);
            s0 = fmaf(v00, w3s[c], fmaf(v01, w3s[c + 1], s0));
            s1 = fmaf(v10, w3s[c], fmaf(v11, w3s[c + 1], s1));
            if (wf) {
                *(float2*)(featbase + (size_t)row0 * FDIM + c) = make_float2(v00, v01);
                *(float2*)(featbase + (size_t)row1 * FDIM + c) = make_float2(v10, v11);
            }
        }
        s0 += __shfl_xor_sync(0xffffffffu, s0, 1);
        s0 += __shfl_xor_sync(0xffffffffu, s0, 2);
        s1 += __shfl_xor_sync(0xffffffffu, s1, 1);
        s1 += __shfl_xor_sync(0xffffffffu, s1, 2);
        if ((lane & 3) == 0) {
            out[(size_t)i * NDRUG + row0] = 1.f / (1.f + expf(-(b3v + s0)));
            out[(size_t)i * NDRUG + row1] = 1.f / (1.f + expf(-(b3v + s1)));
        }
    }
}

// ---------------- launch ----------------
extern "C" void kernel_launch(void* const* d_in, const int* in_sizes, int n_in,
                              void* d_out, int out_size) {
    if (n_in < 8) return;
    const float* cellpos = (const float*)d_in[0];
    const float* drugpos = (const float*)d_in[1];
    const float* W1      = (const float*)d_in[2];
    const float* b1      = (const float*)d_in[3];
    const float* W2      = (const float*)d_in[4];
    const float* b2      = (const float*)d_in[5];
    const float* W3      = (const float*)d_in[6];
    const float* b3      = (const float*)d_in[7];
    float* out = (float*)d_out;

    layer1_v2<<<104, 256>>>(cellpos, drugpos, W1, W2);
    graphcdr_main<<<dim3(NCELL, 2), 128>>>(b1, b2, W3, b3, out, out_size);
}